// round 11
// baseline (speedup 1.0000x reference)
#include <cuda_runtime.h>
#include <math.h>

#define BB 8
#define TT 4096
#define EE 64
#define DD 8
#define TILE 256
#define RPW 4
#define WARPS 8
#define ROWS_PER_GROUP (RPW*WARPS)           /* 32 */
#define GROUPS_PER_BATCH (TT/ROWS_PER_GROUP) /* 128 */
#define NUNITS (BB*GROUPS_PER_BATCH)         /* 1024 */
#define GRID_ATTN 304                        /* 152 SMs x 2 CTAs */

typedef unsigned long long u64;

__device__ __forceinline__ u64 fmul2(u64 a, u64 b){ u64 d; asm("mul.rn.f32x2 %0,%1,%2;":"=l"(d):"l"(a),"l"(b)); return d; }
__device__ __forceinline__ u64 ffma2(u64 a, u64 b, u64 c){ u64 d; asm("fma.rn.f32x2 %0,%1,%2,%3;":"=l"(d):"l"(a),"l"(b),"l"(c)); return d; }
__device__ __forceinline__ void unpack2(u64 a, float& l, float& h){ asm("mov.b64 {%0,%1},%2;":"=f"(l),"=f"(h):"l"(a)); }
__device__ __forceinline__ u64 pack2(float l, float h){ u64 d; asm("mov.b64 %0,{%1,%2};":"=l"(d):"f"(l),"f"(h)); return d; }
__device__ __forceinline__ float ex2f(float x){ float r; asm("ex2.approx.f32 %0,%1;":"=f"(r):"f"(x)); return r; }

__device__ __forceinline__ void cpasync16(float* dst, const float* src){
    unsigned s = (unsigned)__cvta_generic_to_shared(dst);
    asm volatile("cp.async.cg.shared.global [%0], [%1], 16;" :: "r"(s), "l"(src));
}
__device__ __forceinline__ void cpcommit(){ asm volatile("cp.async.commit_group;"); }
__device__ __forceinline__ void cpwait1(){ asm volatile("cp.async.wait_group 1;"); }
__device__ __forceinline__ void cpwait0(){ asm volatile("cp.async.wait_group 0;"); }

// scratch (no allocations allowed)
__device__ __align__(16) float g_q[BB*TT*DD];
__device__ __align__(16) float g_kt[BB*TT*DD];   // kt[b][t2][i] = reshaped-K column layout
__device__ __align__(16) float g_v[BB*TT*DD];
__device__ int g_ctr;                            // work-unit counter (reset by proj)

// -------------------- projection: q, kt, v from x --------------------
__global__ __launch_bounds__(256) void proj_kernel(
    const float* __restrict__ x,
    const float* __restrict__ Wq, const float* __restrict__ bq,
    const float* __restrict__ Wk, const float* __restrict__ bk,
    const float* __restrict__ Wv, const float* __restrict__ bv)
{
    if (blockIdx.x == 0 && threadIdx.x == 0) g_ctr = 0;  // reset scheduler

    __shared__ __align__(16) float sW[3][EE][DD];
    __shared__ float sb[3][DD];
    int tid = threadIdx.x;
    for (int i = tid; i < EE*DD; i += 256) {
        sW[0][i>>3][i&7] = Wq[i];
        sW[1][i>>3][i&7] = Wk[i];
        sW[2][i>>3][i&7] = Wv[i];
    }
    if (tid < DD) { sb[0][tid]=bq[tid]; sb[1][tid]=bk[tid]; sb[2][tid]=bv[tid]; }
    __syncthreads();

    int row = blockIdx.x*256 + tid;       // 0 .. B*T-1
    int b = row >> 12;
    int t = row & (TT-1);

    float aq[8], ak[8], av[8];
    #pragma unroll
    for (int i=0;i<8;i++){ aq[i]=sb[0][i]; ak[i]=sb[1][i]; av[i]=sb[2][i]; }

    const float4* xr = (const float4*)(x + (size_t)row*EE);
    #pragma unroll
    for (int j4 = 0; j4 < 16; j4++) {
        float4 xv = xr[j4];
        float xs[4] = {xv.x, xv.y, xv.z, xv.w};
        #pragma unroll
        for (int m = 0; m < 4; m++) {
            int jj = j4*4 + m;
            float xsm = xs[m];
            #pragma unroll
            for (int i = 0; i < 8; i++) {
                aq[i] = fmaf(xsm, sW[0][jj][i], aq[i]);
                ak[i] = fmaf(xsm, sW[1][jj][i], ak[i]);
                av[i] = fmaf(xsm, sW[2][jj][i], av[i]);
            }
        }
    }

    float4* qo = (float4*)(g_q + (size_t)row*8);
    qo[0] = make_float4(aq[0],aq[1],aq[2],aq[3]);
    qo[1] = make_float4(aq[4],aq[5],aq[6],aq[7]);
    float4* vo = (float4*)(g_v + (size_t)row*8);
    vo[0] = make_float4(av[0],av[1],av[2],av[3]);
    vo[1] = make_float4(av[4],av[5],av[6],av[7]);

    // reshape scatter: flat idx t*8+c -> i = t>>9, j = (t&511)*8+c
    int ich = t >> 9;
    int j0  = (t & 511) * 8;
    float* kb = g_kt + (size_t)b*TT*8;
    #pragma unroll
    for (int c = 0; c < 8; c++)
        kb[(size_t)(j0 + c)*8 + ich] = ak[c];
}

// -------------------- attention --------------------
// Persistent blocks pop 32-row groups (8 warps x 4 rows) LPT-descending from a
// global counter. 2 CTAs/SM (regs<=128 via launch_bounds(256,2)) -> 16 warps/SM
// for latency hiding (R9 showed issue=46% at 8 warps was the limiter).
// Tiles of 256 columns double-buffered via cp.async. Dot + accumulate in
// packed f32x2; q pre-scaled by (1/sqrt8)*log2e so exp is a bare ex2; masking
// is the integer causal compare only (boundary tiles).
__global__ __launch_bounds__(256, 2) void attn_kernel(float* __restrict__ out)
{
    __shared__ __align__(16) float sm[2][TILE*20];
    __shared__ int s_u;

    const int tid  = threadIdx.x;
    const int lane = tid & 31;
    const int w    = tid >> 5;

    // per-thread cooperative-load coordinates (4 x 16B chunks per tile)
    int l_col[4], l_part[4];
    #pragma unroll
    for (int kk = 0; kk < 4; kk++) {
        int chunk = tid + kk*256;
        l_col[kk]  = chunk >> 2;
        l_part[kk] = chunk & 3;
    }

    const float CSCALE = 0.35355339059327373f * 1.4426950408889634f;

    for (;;) {
        __syncthreads();   // protect s_u from previous iteration's readers
        if (tid == 0) s_u = atomicAdd(&g_ctr, 1);
        __syncthreads();
        const int u = s_u;
        if (u >= NUNITS) return;

        const int b = u & (BB-1);
        const int g = (GROUPS_PER_BATCH-1) - (u >> 3);   // descending size (LPT)

        const float* qb  = g_q  + (size_t)b*TT*8;
        const float* ktb = g_kt + (size_t)b*TT*8;
        const float* vb  = g_v  + (size_t)b*TT*8;
        float*       ob  = out  + (size_t)b*TT*8;

        const int r0 = g*ROWS_PER_GROUP + w*RPW;

        u64 q2[RPW][4];
        #pragma unroll
        for (int r = 0; r < RPW; r++) {
            const float* qr = qb + (size_t)(r0+r)*8;
            float4 a = *(const float4*)(qr);
            float4 c = *(const float4*)(qr + 4);
            q2[r][0] = pack2(a.x*CSCALE, a.y*CSCALE);
            q2[r][1] = pack2(a.z*CSCALE, a.w*CSCALE);
            q2[r][2] = pack2(c.x*CSCALE, c.y*CSCALE);
            q2[r][3] = pack2(c.z*CSCALE, c.w*CSCALE);
        }

        u64 acc2[RPW][4];
        float lsum[RPW];
        #pragma unroll
        for (int r = 0; r < RPW; r++) {
            lsum[r] = 0.f;
            #pragma unroll
            for (int i = 0; i < 4; i++) acc2[r][i] = 0ull;
        }

        const int ntiles = (g*ROWS_PER_GROUP + ROWS_PER_GROUP - 1) / TILE + 1;

        // prologue: async-load tile 0 into buffer 0
        #pragma unroll
        for (int kk = 0; kk < 4; kk++) {
            const float* src = (l_part[kk] < 2 ? ktb : vb)
                               + (size_t)l_col[kk]*8 + (l_part[kk] & 1)*4;
            cpasync16(&sm[0][l_col[kk]*20 + l_part[kk]*4], src);
        }
        cpcommit();

        for (int ti = 0; ti < ntiles; ti++) {
            const int tbase = ti * TILE;
            // prefetch next tile into the other buffer, then wait for current
            if (ti + 1 < ntiles) {
                const int nb = tbase + TILE;
                #pragma unroll
                for (int kk = 0; kk < 4; kk++) {
                    const float* src = (l_part[kk] < 2 ? ktb : vb)
                                       + (size_t)(nb + l_col[kk])*8 + (l_part[kk] & 1)*4;
                    cpasync16(&sm[(ti+1)&1][l_col[kk]*20 + l_part[kk]*4], src);
                }
                cpcommit();
                cpwait1();
            } else {
                cpwait0();
            }
            __syncthreads();   // current buffer visible to all
            const float* buf = sm[ti & 1];

            if (tbase + TILE - 1 <= r0) {
                // fully unmasked tile
                #pragma unroll 2
                for (int it = 0; it < TILE/32; it++) {
                    const float* cp = buf + (it*32 + lane)*20;
                    ulonglong2 ka  = *(const ulonglong2*)(cp);
                    ulonglong2 kb2 = *(const ulonglong2*)(cp + 4);
                    float p[RPW];
                    #pragma unroll
                    for (int r = 0; r < RPW; r++) {
                        u64 d2 = fmul2(q2[r][0], ka.x);
                        d2 = ffma2(q2[r][1], ka.y, d2);
                        d2 = ffma2(q2[r][2], kb2.x, d2);
                        d2 = ffma2(q2[r][3], kb2.y, d2);
                        float tl, th; unpack2(d2, tl, th);
                        p[r] = ex2f(tl + th);
                    }
                    ulonglong2 va  = *(const ulonglong2*)(cp + 8);
                    ulonglong2 vb2 = *(const ulonglong2*)(cp + 12);
                    #pragma unroll
                    for (int r = 0; r < RPW; r++) {
                        float pr = p[r];
                        lsum[r] += pr;
                        u64 p2 = pack2(pr, pr);
                        acc2[r][0] = ffma2(p2, va.x,  acc2[r][0]);
                        acc2[r][1] = ffma2(p2, va.y,  acc2[r][1]);
                        acc2[r][2] = ffma2(p2, vb2.x, acc2[r][2]);
                        acc2[r][3] = ffma2(p2, vb2.y, acc2[r][3]);
                    }
                }
            } else {
                // boundary tile: per-row causal guard only
                #pragma unroll 2
                for (int it = 0; it < TILE/32; it++) {
                    const int t2 = tbase + it*32 + lane;
                    const float* cp = buf + (it*32 + lane)*20;
                    ulonglong2 ka  = *(const ulonglong2*)(cp);
                    ulonglong2 kb2 = *(const ulonglong2*)(cp + 4);
                    float p[RPW];
                    #pragma unroll
                    for (int r = 0; r < RPW; r++) {
                        u64 d2 = fmul2(q2[r][0], ka.x);
                        d2 = ffma2(q2[r][1], ka.y, d2);
                        d2 = ffma2(q2[r][2], kb2.x, d2);
                        d2 = ffma2(q2[r][3], kb2.y, d2);
                        float tl, th; unpack2(d2, tl, th);
                        float pr = ex2f(tl + th);
                        p[r] = (t2 <= r0 + r) ? pr : 0.f;
                    }
                    ulonglong2 va  = *(const ulonglong2*)(cp + 8);
                    ulonglong2 vb2 = *(const ulonglong2*)(cp + 12);
                    #pragma unroll
                    for (int r = 0; r < RPW; r++) {
                        float pr = p[r];
                        lsum[r] += pr;
                        u64 p2 = pack2(pr, pr);
                        acc2[r][0] = ffma2(p2, va.x,  acc2[r][0]);
                        acc2[r][1] = ffma2(p2, va.y,  acc2[r][1]);
                        acc2[r][2] = ffma2(p2, vb2.x, acc2[r][2]);
                        acc2[r][3] = ffma2(p2, vb2.y, acc2[r][3]);
                    }
                }
            }
            __syncthreads();   // everyone done reading buf before it is refilled
        }

        // epilogue: warp-reduce (l, acc[8]) per row, lane 0 writes
        #pragma unroll
        for (int r = 0; r < RPW; r++) {
            float vals[9];
            #pragma unroll
            for (int i = 0; i < 4; i++) unpack2(acc2[r][i], vals[2*i], vals[2*i+1]);
            vals[8] = lsum[r];
            #pragma unroll
            for (int i = 0; i < 9; i++) {
                #pragma unroll
                for (int o = 16; o > 0; o >>= 1)
                    vals[i] += __shfl_xor_sync(0xffffffffu, vals[i], o);
            }
            if (lane == 0) {
                float inv = 1.f / vals[8];
                float4 o0 = make_float4(vals[0]*inv, vals[1]*inv, vals[2]*inv, vals[3]*inv);
                float4 o1 = make_float4(vals[4]*inv, vals[5]*inv, vals[6]*inv, vals[7]*inv);
                *(float4*)(ob + (size_t)(r0+r)*8)     = o0;
                *(float4*)(ob + (size_t)(r0+r)*8 + 4) = o1;
            }
        }
    }
}

extern "C" void kernel_launch(void* const* d_in, const int* in_sizes, int n_in,
                              void* d_out, int out_size)
{
    (void)in_sizes; (void)n_in; (void)out_size;
    const float* x  = (const float*)d_in[0];
    const float* Wq = (const float*)d_in[1];
    const float* bq = (const float*)d_in[2];
    const float* Wk = (const float*)d_in[3];
    const float* bk = (const float*)d_in[4];
    const float* Wv = (const float*)d_in[5];
    const float* bv = (const float*)d_in[6];
    float* out = (float*)d_out;

    proj_kernel<<<(BB*TT)/256, 256>>>(x, Wq, bq, Wk, bk, Wv, bv);
    attn_kernel<<<GRID_ATTN, 256>>>(out);
}

// round 15
// speedup vs baseline: 1.8429x; 1.8429x over previous
#include <cuda_runtime.h>
#include <cuda_fp16.h>
#include <math.h>
#include <stdint.h>

typedef unsigned int u32;
typedef unsigned long long u64;

#define BB 8
#define TT 4096
#define EE 64
#define DD 8
#define QBLK 128
#define NQB 32              /* Q-blocks per batch */
#define TILEN 128           /* columns per tile */
#define SEGT 8              /* max tiles per segment (1024 cols) */
#define NSEGSLOT 4
#define SEGS_PER_BATCH 80   /* sum over qb of ceil((qb+1)/8) */
#define NUNITS (BB*SEGS_PER_BATCH)   /* 640 */

__device__ __forceinline__ float ex2f(float x){ float r; asm("ex2.approx.f32 %0,%1;":"=f"(r):"f"(x)); return r; }
__device__ __forceinline__ u32 tf32r(float x){ u32 r; asm("cvt.rna.tf32.f32 %0,%1;":"=r"(r):"f"(x)); return r; }
__device__ __forceinline__ u32 fu(float x){ return __float_as_uint(x); }

/* D += A*B, m16n8k8 tf32 (A row-major frag, B col-major frag) */
__device__ __forceinline__ void mma_tf32(float* c, const u32* a, u32 b0, u32 b1){
    asm volatile("mma.sync.aligned.m16n8k8.row.col.f32.tf32.tf32.f32 "
        "{%0,%1,%2,%3}, {%4,%5,%6,%7}, {%8,%9}, {%0,%1,%2,%3};"
        : "+f"(c[0]),"+f"(c[1]),"+f"(c[2]),"+f"(c[3])
        : "r"(a[0]),"r"(a[1]),"r"(a[2]),"r"(a[3]), "r"(b0),"r"(b1));
}
/* D += A*B, m16n8k16 f16 inputs, f32 accum */
__device__ __forceinline__ void mma_f16(float* c, u32 a0,u32 a1,u32 a2,u32 a3, u32 b0,u32 b1){
    asm volatile("mma.sync.aligned.m16n8k16.row.col.f32.f16.f16.f32 "
        "{%0,%1,%2,%3}, {%4,%5,%6,%7}, {%8,%9}, {%0,%1,%2,%3};"
        : "+f"(c[0]),"+f"(c[1]),"+f"(c[2]),"+f"(c[3])
        : "r"(a0),"r"(a1),"r"(a2),"r"(a3), "r"(b0),"r"(b1));
}
__device__ __forceinline__ u32 h2pack(float lo, float hi){
    __half2 h = __floats2half2_rn(lo, hi);
    return *(u32*)&h;
}

// scratch (no allocations allowed)
__device__ __align__(16) float g_q[BB*TT*DD];    // pre-scaled by (1/sqrt8)*log2e
__device__ __align__(16) float g_kt[BB*TT*DD];   // kt[b][t2][i] reshaped-K columns
__device__ __align__(16) float g_v[BB*TT*DD];
__device__ __align__(16) float g_part[BB*NQB*NSEGSLOT][QBLK][12]; // o[0..7], lsum at [8]

// -------------------- projection --------------------
__global__ __launch_bounds__(256) void proj_kernel(
    const float* __restrict__ x,
    const float* __restrict__ Wq, const float* __restrict__ bq,
    const float* __restrict__ Wk, const float* __restrict__ bk,
    const float* __restrict__ Wv, const float* __restrict__ bv)
{
    __shared__ __align__(16) float sW[3][EE][DD];
    __shared__ float sb[3][DD];
    int tid = threadIdx.x;
    for (int i = tid; i < EE*DD; i += 256) {
        sW[0][i>>3][i&7] = Wq[i];
        sW[1][i>>3][i&7] = Wk[i];
        sW[2][i>>3][i&7] = Wv[i];
    }
    if (tid < DD) { sb[0][tid]=bq[tid]; sb[1][tid]=bk[tid]; sb[2][tid]=bv[tid]; }
    __syncthreads();

    int row = blockIdx.x*256 + tid;
    int b = row >> 12;
    int t = row & (TT-1);

    float aq[8], ak[8], av[8];
    #pragma unroll
    for (int i=0;i<8;i++){ aq[i]=sb[0][i]; ak[i]=sb[1][i]; av[i]=sb[2][i]; }

    const float4* xr = (const float4*)(x + (size_t)row*EE);
    #pragma unroll
    for (int j4 = 0; j4 < 16; j4++) {
        float4 xv = xr[j4];
        float xs[4] = {xv.x, xv.y, xv.z, xv.w};
        #pragma unroll
        for (int m = 0; m < 4; m++) {
            int jj = j4*4 + m;
            float xsm = xs[m];
            #pragma unroll
            for (int i = 0; i < 8; i++) {
                aq[i] = fmaf(xsm, sW[0][jj][i], aq[i]);
                ak[i] = fmaf(xsm, sW[1][jj][i], ak[i]);
                av[i] = fmaf(xsm, sW[2][jj][i], av[i]);
            }
        }
    }

    const float CL = 0.35355339059327373f * 1.4426950408889634f;
    float4* qo = (float4*)(g_q + (size_t)row*8);
    qo[0] = make_float4(aq[0]*CL,aq[1]*CL,aq[2]*CL,aq[3]*CL);
    qo[1] = make_float4(aq[4]*CL,aq[5]*CL,aq[6]*CL,aq[7]*CL);
    float4* vo = (float4*)(g_v + (size_t)row*8);
    vo[0] = make_float4(av[0],av[1],av[2],av[3]);
    vo[1] = make_float4(av[4],av[5],av[6],av[7]);

    int ich = t >> 9;
    int j0  = (t & 511) * 8;
    float* kb = g_kt + (size_t)b*TT*8;
    #pragma unroll
    for (int c = 0; c < 8; c++)
        kb[(size_t)(j0 + c)*8 + ich] = ak[c];
}

// -------------------- attention (mma.sync flash, segmented) --------------------
// Unit = (batch, Q-block of 128 rows, segment of <=8 column-tiles). 640 units,
// enumerated descending-work (HW greedy ~ LPT). 8 warps x 16 rows each.
// GEMM1 tf32 m16n8k8 hi/lo split (3 mma, score err ~2^-22); softmax in
// registers (bare ex2 since q pre-scaled by (1/sqrt8)*log2e; causal select on
// the diagonal tile only); P packed to f16x2 register-locally (D-fragment of
// GEMM1 maps 1:1 onto A-fragment of GEMM2); GEMM2 f16 m16n8k16 f32-accum.
// Partial (O, lsum) per segment to g_part; combine kernel sums + normalizes.
__global__ __launch_bounds__(256) void attn_kernel()
{
    __shared__ __align__(16) float s_khl[2][TILEN][20]; // kh[0..7], kl[8..15], pad
    __shared__ __align__(16) u32   s_vp[2][64][8];      // f16x2 (v[2c][n], v[2c+1][n])

    const int tid = threadIdx.x, lane = tid & 31, w = tid >> 5;
    const int m = lane & 3, r4 = lane >> 2;

    // blockIdx -> (b, qb, seg), qb descending (bounded decode, <=32 iters)
    const int b = blockIdx.x & 7;
    int qb, seg;
    {
        int rem = blockIdx.x >> 3;   // 0..79
        int q = NQB - 1;
        for (;;) {
            int ns = (q + 8) >> 3;
            if (rem < ns) { seg = rem; break; }
            rem -= ns; q--;
        }
        qb = q;
    }
    const int t0 = seg * SEGT;
    const int ntl = min(SEGT, qb + 1 - t0);

    const float* ktb = g_kt + (size_t)b*TT*8;
    const float* vbp = g_v  + (size_t)b*TT*8;

    // Q fragments (rows qb*128 + w*16 + {r4, r4+8}; cols {m, m+4}), hi/lo split
    u32 qh[4], ql[4];
    {
        const float* qp = g_q + ((size_t)b*TT + (size_t)qb*QBLK + w*16) * 8;
        float qv[4];
        qv[0] = qp[(size_t)r4*8 + m];
        qv[1] = qp[(size_t)(r4+8)*8 + m];
        qv[2] = qp[(size_t)r4*8 + m + 4];
        qv[3] = qp[(size_t)(r4+8)*8 + m + 4];
        #pragma unroll
        for (int i = 0; i < 4; i++) {
            qh[i] = tf32r(qv[i]);
            ql[i] = tf32r(qv[i] - __uint_as_float(qh[i]));
        }
    }

    float o[4] = {0.f,0.f,0.f,0.f};
    float ls0 = 0.f, ls1 = 0.f;

    // tile prefetch registers
    float4 pk0, pk1, pv00, pv01, pv10, pv11;

    // prologue LDG tile 0
    {
        int colb = t0 * TILEN;
        if (tid < 128) {
            const float* s = ktb + (size_t)(colb + tid)*8;
            pk0 = *(const float4*)s; pk1 = *(const float4*)(s+4);
        } else if (tid < 192) {
            const float* s = vbp + (size_t)(colb + (tid-128)*2)*8;
            pv00 = *(const float4*)s;     pv01 = *(const float4*)(s+4);
            pv10 = *(const float4*)(s+8); pv11 = *(const float4*)(s+12);
        }
    }

    for (int t = 0; t < ntl; t++) {
        const int bf = t & 1;
        // STS prefetched tile
        if (tid < 128) {
            float kf[8] = {pk0.x,pk0.y,pk0.z,pk0.w,pk1.x,pk1.y,pk1.z,pk1.w};
            float hi[8], lo[8];
            #pragma unroll
            for (int d = 0; d < 8; d++) {
                u32 h = tf32r(kf[d]);
                hi[d] = __uint_as_float(h);
                lo[d] = __uint_as_float(tf32r(kf[d] - __uint_as_float(h)));
            }
            float* row = &s_khl[bf][tid][0];
            *(float4*)(row)     = make_float4(hi[0],hi[1],hi[2],hi[3]);
            *(float4*)(row+4)   = make_float4(hi[4],hi[5],hi[6],hi[7]);
            *(float4*)(row+8)   = make_float4(lo[0],lo[1],lo[2],lo[3]);
            *(float4*)(row+12)  = make_float4(lo[4],lo[5],lo[6],lo[7]);
        } else if (tid < 192) {
            int c = tid - 128;
            float a[8] = {pv00.x,pv00.y,pv00.z,pv00.w,pv01.x,pv01.y,pv01.z,pv01.w};
            float d[8] = {pv10.x,pv10.y,pv10.z,pv10.w,pv11.x,pv11.y,pv11.z,pv11.w};
            u32 pk[8];
            #pragma unroll
            for (int n = 0; n < 8; n++) pk[n] = h2pack(a[n], d[n]);
            *(uint4*)&s_vp[bf][c][0] = make_uint4(pk[0],pk[1],pk[2],pk[3]);
            *(uint4*)&s_vp[bf][c][4] = make_uint4(pk[4],pk[5],pk[6],pk[7]);
        }
        __syncthreads();

        // prefetch next tile (into registers; STS next iteration)
        if (t + 1 < ntl) {
            int colb = (t0 + t + 1) * TILEN;
            if (tid < 128) {
                const float* s = ktb + (size_t)(colb + tid)*8;
                pk0 = *(const float4*)s; pk1 = *(const float4*)(s+4);
            } else if (tid < 192) {
                const float* s = vbp + (size_t)(colb + (tid-128)*2)*8;
                pv00 = *(const float4*)s;     pv01 = *(const float4*)(s+4);
                pv10 = *(const float4*)(s+8); pv11 = *(const float4*)(s+12);
            }
        }

        const bool diag = (t0 + t == qb);
        const int il0 = w*16 + r4;       // local row (block-local causal compare)

        #pragma unroll
        for (int ch = 0; ch < 8; ch++) {
            float c0[4] = {0.f,0.f,0.f,0.f};
            float c1[4] = {0.f,0.f,0.f,0.f};
            {
                int n = (ch<<4) + r4;
                u32 bh0 = fu(s_khl[bf][n][m]),   bh1 = fu(s_khl[bf][n][m+4]);
                u32 bl0 = fu(s_khl[bf][n][8+m]), bl1 = fu(s_khl[bf][n][12+m]);
                mma_tf32(c0, qh, bh0, bh1);
                mma_tf32(c0, ql, bh0, bh1);
                mma_tf32(c0, qh, bl0, bl1);
            }
            {
                int n = (ch<<4) + 8 + r4;
                u32 bh0 = fu(s_khl[bf][n][m]),   bh1 = fu(s_khl[bf][n][m+4]);
                u32 bl0 = fu(s_khl[bf][n][8+m]), bl1 = fu(s_khl[bf][n][12+m]);
                mma_tf32(c1, qh, bh0, bh1);
                mma_tf32(c1, ql, bh0, bh1);
                mma_tf32(c1, qh, bl0, bl1);
            }
            float p00 = ex2f(c0[0]), p01 = ex2f(c0[1]);
            float p02 = ex2f(c0[2]), p03 = ex2f(c0[3]);
            float p10 = ex2f(c1[0]), p11 = ex2f(c1[1]);
            float p12 = ex2f(c1[2]), p13 = ex2f(c1[3]);
            if (diag) {
                int jb = (ch<<4) + 2*m;
                p00 = (jb     <= il0)   ? p00 : 0.f;
                p01 = (jb+1   <= il0)   ? p01 : 0.f;
                p02 = (jb     <= il0+8) ? p02 : 0.f;
                p03 = (jb+1   <= il0+8) ? p03 : 0.f;
                p10 = (jb+8   <= il0)   ? p10 : 0.f;
                p11 = (jb+9   <= il0)   ? p11 : 0.f;
                p12 = (jb+8   <= il0+8) ? p12 : 0.f;
                p13 = (jb+9   <= il0+8) ? p13 : 0.f;
            }
            ls0 += p00 + p01 + p10 + p11;
            ls1 += p02 + p03 + p12 + p13;
            u32 a0 = h2pack(p00, p01);
            u32 a1 = h2pack(p02, p03);
            u32 a2 = h2pack(p10, p11);
            u32 a3 = h2pack(p12, p13);
            u32 b0 = s_vp[bf][(ch<<3) + m][r4];
            u32 b1 = s_vp[bf][(ch<<3) + m + 4][r4];
            mma_f16(o, a0, a1, a2, a3, b0, b1);
        }
        __syncthreads();
    }

    // quad-reduce lsum (lanes sharing a row: xor 1, 2)
    ls0 += __shfl_xor_sync(0xffffffffu, ls0, 1);
    ls0 += __shfl_xor_sync(0xffffffffu, ls0, 2);
    ls1 += __shfl_xor_sync(0xffffffffu, ls1, 1);
    ls1 += __shfl_xor_sync(0xffffffffu, ls1, 2);

    const int slot = (b*NQB + qb)*NSEGSLOT + seg;
    float* pr0 = &g_part[slot][w*16 + r4][0];
    float* pr1 = &g_part[slot][w*16 + r4 + 8][0];
    pr0[2*m] = o[0];  pr0[2*m+1] = o[1];
    pr1[2*m] = o[2];  pr1[2*m+1] = o[3];
    if (m == 0) { pr0[8] = ls0; pr1[8] = ls1; }
}

// -------------------- combine: sum segments, normalize --------------------
__global__ __launch_bounds__(256) void combine_kernel(float* __restrict__ out)
{
    int rid = blockIdx.x*256 + threadIdx.x;   // 0 .. BB*TT-1
    int b = rid >> 12, t = rid & (TT-1);
    int qb = t >> 7, r = t & 127;
    int ns = (qb + 8) >> 3;
    int slot0 = (b*NQB + qb)*NSEGSLOT;
    float acc[9];
    #pragma unroll
    for (int k = 0; k < 9; k++) acc[k] = g_part[slot0][r][k];
    for (int s = 1; s < ns; s++) {
        #pragma unroll
        for (int k = 0; k < 9; k++) acc[k] += g_part[slot0+s][r][k];
    }
    float inv = 1.f / acc[8];
    float* orow = out + (size_t)rid*8;
    *(float4*)orow     = make_float4(acc[0]*inv, acc[1]*inv, acc[2]*inv, acc[3]*inv);
    *(float4*)(orow+4) = make_float4(acc[4]*inv, acc[5]*inv, acc[6]*inv, acc[7]*inv);
}

extern "C" void kernel_launch(void* const* d_in, const int* in_sizes, int n_in,
                              void* d_out, int out_size)
{
    (void)in_sizes; (void)n_in; (void)out_size;
    const float* x  = (const float*)d_in[0];
    const float* Wq = (const float*)d_in[1];
    const float* bq = (const float*)d_in[2];
    const float* Wk = (const float*)d_in[3];
    const float* bk = (const float*)d_in[4];
    const float* Wv = (const float*)d_in[5];
    const float* bv = (const float*)d_in[6];
    float* out = (float*)d_out;

    proj_kernel<<<(BB*TT)/256, 256>>>(x, Wq, bq, Wk, bk, Wv, bv);
    attn_kernel<<<NUNITS, 256>>>();
    combine_kernel<<<(BB*TT)/256, 256>>>(out);
}